// round 11
// baseline (speedup 1.0000x reference)
#include <cuda_runtime.h>
#include <math.h>
#include <stdint.h>

// ContrastLoss: B=4, C=4096, K=1.
//
// lse_pairs_b   = log(sum_{lab=0} e^{pred}) + log(sum_{lab=1} e^{-pred})
// loss_contrast = (1/B) * sum_b logaddexp(lse_pairs_b, 0)
// loss_aux      = (1/B) * sum_b mean_c (aux - aux_label)^2
//
// R11: 4-CTA cluster x 1024 threads, one CTA per batch, 4 elems/thread.
// Each CTA finalizes its batch loss entirely locally; only 2 floats cross
// CTAs (DSMEM into rank 0), one cluster barrier, rank 0 sums 4 float2s in
// fixed order. Deterministic.

#define FULL 0xFFFFFFFFu
#define NBLK 4
#define NTHR 1024
#define WPB  (NTHR / 32)     // 32 warps per CTA

__device__ __forceinline__ uint32_t smem_u32(const void* p) {
    uint32_t a;
    asm("{ .reg .u64 t; cvta.to.shared.u64 t, %1; cvt.u32.u64 %0, t; }"
        : "=r"(a) : "l"(p));
    return a;
}

__device__ __forceinline__ void acc_elem(float v, int lab, float& sn, float& sp) {
    float fl = (float)lab;
    float e  = __expf(v * fmaf(-2.f, fl, 1.f));  // exp(+v) if lab==0 else exp(-v)
    sn = fmaf(e, 1.f - fl, sn);
    sp = fmaf(e, fl, sp);
}

__global__ __launch_bounds__(NTHR, 1) __cluster_dims__(NBLK, 1, 1)
void contrast_loss_kernel(const float* __restrict__ contrast,
                          const int*   __restrict__ label,
                          const float* __restrict__ aux,
                          const float* __restrict__ aux_label,
                          float* __restrict__ out) {
    __shared__ float4 swarp[WPB];     // per-warp partials {sn, sp, ax, 0}
    __shared__ float2 sres[NBLK];     // per-batch results (used in rank 0 only)

    int tid = threadIdx.x;
    uint32_t rank;
    asm("mov.u32 %0, %%cluster_ctarank;" : "=r"(rank));

    // CTA rank == batch index. 4096 elems / 1024 threads = 4 per thread.
    int base = (int)rank * 4096 + tid * 4;

    float4 c  = *reinterpret_cast<const float4*>(contrast + base);
    int4   l  = *reinterpret_cast<const int4*>(label + base);
    float4 a  = *reinterpret_cast<const float4*>(aux + base);
    float4 al = *reinterpret_cast<const float4*>(aux_label + base);

    float sn = 0.f, sp = 0.f, ax = 0.f;

    acc_elem(c.x, l.x, sn, sp);
    acc_elem(c.y, l.y, sn, sp);
    acc_elem(c.z, l.z, sn, sp);
    acc_elem(c.w, l.w, sn, sp);

    float d;
    d = a.x - al.x; ax = fmaf(d, d, ax);
    d = a.y - al.y; ax = fmaf(d, d, ax);
    d = a.z - al.z; ax = fmaf(d, d, ax);
    d = a.w - al.w; ax = fmaf(d, d, ax);

    // Warp reduction (32 warps per CTA).
    #pragma unroll
    for (int o = 16; o > 0; o >>= 1) {
        sn += __shfl_down_sync(FULL, sn, o);
        sp += __shfl_down_sync(FULL, sp, o);
        ax += __shfl_down_sync(FULL, ax, o);
    }

    int w = tid >> 5;
    if ((tid & 31) == 0) {
        swarp[w] = make_float4(sn, sp, ax, 0.f);
    }
    __syncthreads();

    // Warp 0: fully parallel reduce of the 32 warp partials (lane l owns
    // slot l), then lane 0 finalizes this batch's loss and ships 2 floats
    // into rank 0's smem via DSMEM.
    if (tid < 32) {
        float4 p = swarp[tid];
        float bn = p.x, bp = p.y, ba = p.z;
        #pragma unroll
        for (int o = 16; o > 0; o >>= 1) {
            bn += __shfl_down_sync(FULL, bn, o);
            bp += __shfl_down_sync(FULL, bp, o);
            ba += __shfl_down_sync(FULL, ba, o);
        }
        if (tid == 0) {
            // Empty class -> bn or bp == 0 -> lse = -inf -> contras = 0.
            float lse     = __logf(bn) + __logf(bp);
            float contras = fmaxf(lse, 0.f) + log1pf(__expf(-fabsf(lse)));
            float laux    = ba * (1.0f / 4096.0f);

            uint32_t local = smem_u32(&sres[rank]);
            uint32_t rem;
            asm volatile("mapa.shared::cluster.u32 %0, %1, 0;"
                         : "=r"(rem) : "r"(local));
            asm volatile("st.shared::cluster.v2.f32 [%0], {%1, %2};"
                         :: "r"(rem), "f"(contras), "f"(laux) : "memory");
        }
    }

    // One cluster barrier: arrive (release) orders the DSMEM stores;
    // wait (acquire) makes them visible to rank 0.
    asm volatile("barrier.cluster.arrive.aligned;" ::: "memory");
    asm volatile("barrier.cluster.wait.aligned;"   ::: "memory");

    if (rank == 0 && tid == 0) {
        float2 r0 = sres[0], r1 = sres[1], r2 = sres[2], r3 = sres[3];
        float lc = (r0.x + r1.x) + (r2.x + r3.x);   // fixed order: deterministic
        float la = (r0.y + r1.y) + (r2.y + r3.y);
        out[0] = lc * 0.25f;   // / n_items (B=4)
        out[1] = la * 0.25f;
    }
}

extern "C" void kernel_launch(void* const* d_in, const int* in_sizes, int n_in,
                              void* d_out, int out_size) {
    const float* contrast  = (const float*)d_in[0];
    const int*   label     = (const int*)d_in[1];
    const float* aux       = (const float*)d_in[2];
    const float* aux_label = (const float*)d_in[3];
    float* out = (float*)d_out;

    contrast_loss_kernel<<<NBLK, NTHR>>>(contrast, label, aux, aux_label, out);
}